// round 6
// baseline (speedup 1.0000x reference)
#include <cuda_runtime.h>

// AnnularDilatedKNN: B=4, N=4096, C=64, SAMPLE=16, DILATED_RATE=2 -> NSAMPLE=32, K_out=16
// radius^2 = 256.
//
// R6: cell-grid + bitmap rewrite of the query (issue-bound at 69.5% -> reduce work).
//  - build: per-batch counting sort into 20^3 cells (size 17, clamped, conservative
//    vs rounded predicate), cell-sorted SoA + original ids + CSR starts.
//  - query: warp/query scans only the 27-neighborhood (9 contiguous runs), exact
//    verified predicate, hits recorded as bits (original index) in a 4096-bit smem
//    bitmap. "First 31 by index" recovered by popc-prefix + binary search.
//  - gather kernels unchanged from R4/R5.
// Per-candidate arithmetic byte-identical to the rel_err=0.0 verified kernels.

#define NB    4
#define NP    4096
#define KOUT  16
#define QW    16            // queries (warps) per query block
#define NC    20            // cells per axis
#define NCELL (NC * NC * NC)
#define CMIN  (-170.0f)
#define INVCELL (1.0f / 17.0f)

__device__ int   g_ids[NB * NP * KOUT];
__device__ float g_sxs[NB * NP];
__device__ float g_sys[NB * NP];
__device__ float g_szs[NB * NP];
__device__ float g_ssq[NB * NP];
__device__ int   g_sid[NB * NP];
__device__ int   g_cell_start[NB * (NCELL + 1)];

__device__ __forceinline__ float sq3(float x, float y, float z) {
    // jnp.sum(xyz*xyz, -1): left-to-right, separately rounded products (no fma).
    return __fadd_rn(__fadd_rn(__fmul_rn(x, x), __fmul_rn(y, y)), __fmul_rn(z, z));
}

__device__ __forceinline__ int cell1(float v) {
    int c = (int)floorf(__fmul_rn(__fadd_rn(v, -CMIN), INVCELL));
    return min(max(c, 0), NC - 1);
}

// ---------------- build: counting sort into cells, one block per batch ----------------
__global__ __launch_bounds__(1024) void build_kernel(const float* __restrict__ xyz) {
    __shared__ int cnts[NCELL];          // 32000 B
    __shared__ int wsum[32];
    const int b = blockIdx.x, tid = threadIdx.x;
    const int lane = tid & 31, wid = tid >> 5;

    for (int c = tid; c < NCELL; c += 1024) cnts[c] = 0;
    __syncthreads();

    float px[4], py[4], pz[4];
    int pc[4];
    #pragma unroll
    for (int j = 0; j < 4; ++j) {
        const int i = tid + j * 1024;
        const float x = xyz[3 * (b * NP + i) + 0];
        const float y = xyz[3 * (b * NP + i) + 1];
        const float z = xyz[3 * (b * NP + i) + 2];
        px[j] = x; py[j] = y; pz[j] = z;
        const int c = (cell1(z) * NC + cell1(y)) * NC + cell1(x);
        pc[j] = c;
        atomicAdd(&cnts[c], 1);
    }
    __syncthreads();

    // exclusive scan over cnts[NCELL]: 8 cells/thread + block scan of thread sums
    int v[8];
    int s = 0;
    #pragma unroll
    for (int j = 0; j < 8; ++j) {
        const int c = tid * 8 + j;
        const int t = (c < NCELL) ? cnts[c] : 0;
        v[j] = t; s += t;
    }
    int incl = s;
    #pragma unroll
    for (int off = 1; off < 32; off <<= 1) {
        const int t = __shfl_up_sync(0xffffffffu, incl, off);
        if (lane >= off) incl += t;
    }
    if (lane == 31) wsum[wid] = incl;
    __syncthreads();
    if (wid == 0) {
        const int w = wsum[lane];
        int wi = w;
        #pragma unroll
        for (int off = 1; off < 32; off <<= 1) {
            const int t = __shfl_up_sync(0xffffffffu, wi, off);
            if (lane >= off) wi += t;
        }
        wsum[lane] = wi - w;   // exclusive warp offsets
    }
    __syncthreads();
    int run = (incl - s) + wsum[wid];
    #pragma unroll
    for (int j = 0; j < 8; ++j) {
        const int c = tid * 8 + j;
        if (c < NCELL) cnts[c] = run;
        run += v[j];
    }
    __syncthreads();

    for (int c = tid; c < NCELL; c += 1024)
        g_cell_start[b * (NCELL + 1) + c] = cnts[c];
    if (tid == 0) g_cell_start[b * (NCELL + 1) + NCELL] = NP;
    __syncthreads();   // starts published before cnts are mutated as cursors

    #pragma unroll
    for (int j = 0; j < 4; ++j) {
        const int pos = atomicAdd(&cnts[pc[j]], 1);
        const int gi = b * NP + pos;
        g_sxs[gi] = px[j];
        g_sys[gi] = py[j];
        g_szs[gi] = pz[j];
        g_ssq[gi] = sq3(px[j], py[j], pz[j]);
        g_sid[gi] = tid + j * 1024;
    }
}

// ---------------- query: warp per query, 27-cell scan into bitmap ----------------
__global__ __launch_bounds__(32 * QW) void query_kernel(const float* __restrict__ xyz) {
    __shared__ unsigned s_bm[QW][128];   // 4096-bit bitmap per warp
    __shared__ int s_cum[QW][128];       // exclusive per-word hit prefix

    const int warp = threadIdx.x >> 5, lane = threadIdx.x & 31;
    const int q = blockIdx.x * QW + warp;
    const int b = q >> 12, n = q & (NP - 1);
    const int sb = b * NP;

    const float xn = xyz[3 * (sb + n) + 0];
    const float yn = xyz[3 * (sb + n) + 1];
    const float zn = xyz[3 * (sb + n) + 2];
    const float sqn = sq3(xn, yn, zn);
    const int cx = cell1(xn), cy = cell1(yn), cz = cell1(zn);

    #pragma unroll
    for (int j = 0; j < 4; ++j) s_bm[warp][lane * 4 + j] = 0u;
    __syncwarp();

    const int* cs = g_cell_start + b * (NCELL + 1);
    const int x0 = max(cx - 1, 0), x1 = min(cx + 1, NC - 1);
    const int z0 = max(cz - 1, 0), z1 = min(cz + 1, NC - 1);
    const int y0 = max(cy - 1, 0), y1 = min(cy + 1, NC - 1);

    for (int z = z0; z <= z1; ++z) {
        for (int y = y0; y <= y1; ++y) {
            const int row = (z * NC + y) * NC;
            const int s = cs[row + x0];
            const int e = cs[row + x1 + 1];
            for (int i = s + lane; i < e; i += 32) {
                const float xm = g_sxs[sb + i];
                const float ym = g_sys[sb + i];
                const float zm = g_szs[sb + i];
                const float sm = g_ssq[sb + i];
                // byte-identical verified predicate
                const float dot = fmaf(zn, zm, fmaf(yn, ym, __fmul_rn(xn, xm)));
                const float d2  = __fsub_rn(__fadd_rn(sqn, sm), __fmul_rn(2.0f, dot));
                if (d2 < 256.0f) {
                    const int id = g_sid[sb + i];
                    atomicOr(&s_bm[warp][id >> 5], 1u << (id & 31));
                }
            }
        }
    }
    __syncwarp();

    // per-word popc + exclusive prefix across the 128 words
    int c[4];
    int lsum = 0;
    #pragma unroll
    for (int j = 0; j < 4; ++j) {
        c[j] = __popc(s_bm[warp][lane * 4 + j]);
        lsum += c[j];
    }
    int incl = lsum;
    #pragma unroll
    for (int off = 1; off < 32; off <<= 1) {
        const int t = __shfl_up_sync(0xffffffffu, incl, off);
        if (lane >= off) incl += t;
    }
    const int cnt = __shfl_sync(0xffffffffu, incl, 31);
    int base = incl - lsum;
    #pragma unroll
    for (int j = 0; j < 4; ++j) {
        s_cum[warp][lane * 4 + j] = base;
        base += c[j];
    }
    __syncwarp();

    // lanes 0..15 select targets t = {0, 16..30}; pad with hit 0 (center).
    int own = 0;
    const int t = (lane == 0) ? 0 : lane + 15;
    if (lane < 16 && t < cnt) {
        int lo = 0, hi = 127;
        while (lo < hi) {                 // largest word with cum <= t
            const int mid = (lo + hi + 1) >> 1;
            if (s_cum[warp][mid] <= t) lo = mid; else hi = mid - 1;
        }
        unsigned w = s_bm[warp][lo];
        int r = t - s_cum[warp][lo];
        while (r--) w &= (w - 1u);        // drop r lowest set bits
        own = (lo << 5) + (__ffs(w) - 1);
    }
    const int h0 = __shfl_sync(0xffffffffu, own, 0);   // center (cnt >= 1 via self-hit)
    if (lane < 16) {
        const int vsel = (t < cnt) ? own : h0;
        g_ids[(q << 4) + lane] = vsel;
    }
}

// ---------------- gathers (unchanged from R4/R5) ----------------
__global__ __launch_bounds__(256) void gather_xyz_kernel(const float* __restrict__ xyz,
                                                         float* __restrict__ out) {
    const int t  = blockIdx.x * 256 + threadIdx.x;    // b(2)|n(12)|k4(2)
    const int k4 = t & 3;
    const int n  = (t >> 2) & (NP - 1);
    const int b  = t >> 14;
    const int bb = b << 12;
    const int4 id4 = reinterpret_cast<const int4*>(g_ids)[t];
    const int o4 = (n << 2) + k4;

    const float* xb = xyz + 3 * bb;
    const float x0 = xb[3 * id4.x], y0 = xb[3 * id4.x + 1], z0 = xb[3 * id4.x + 2];
    const float x1 = xb[3 * id4.y], y1 = xb[3 * id4.y + 1], z1 = xb[3 * id4.y + 2];
    const float x2 = xb[3 * id4.z], y2 = xb[3 * id4.z + 1], z2 = xb[3 * id4.z + 2];
    const float x3 = xb[3 * id4.w], y3 = xb[3 * id4.w + 1], z3 = xb[3 * id4.w + 2];
    float4* o = reinterpret_cast<float4*>(out);
    o[((b * 3 + 0) << 14) + o4] = make_float4(x0, x1, x2, x3);
    o[((b * 3 + 1) << 14) + o4] = make_float4(y0, y1, y2, y3);
    o[((b * 3 + 2) << 14) + o4] = make_float4(z0, z1, z2, z3);
}

__global__ __launch_bounds__(256) void gather_feat_kernel(const float* __restrict__ feat,
                                                          float* __restrict__ out) {
    const int t  = blockIdx.x * 256 + threadIdx.x;    // b(2)|n(12)|k4(2)|cq(2)
    const int cq = t & 3;
    const int k4 = (t >> 2) & 3;
    const int n  = (t >> 4) & (NP - 1);
    const int b  = t >> 16;
    const int bb = b << 12;
    const int4 id4 = reinterpret_cast<const int4*>(g_ids)[((bb + n) << 2) + k4];
    const int o4 = (n << 2) + k4;

    const float4* f0 = reinterpret_cast<const float4*>(feat) + ((bb + id4.x) << 4) + (cq << 2);
    const float4* f1 = reinterpret_cast<const float4*>(feat) + ((bb + id4.y) << 4) + (cq << 2);
    const float4* f2 = reinterpret_cast<const float4*>(feat) + ((bb + id4.z) << 4) + (cq << 2);
    const float4* f3 = reinterpret_cast<const float4*>(feat) + ((bb + id4.w) << 4) + (cq << 2);

    float4* of = reinterpret_cast<float4*>(out) + ((12 + b * 64 + (cq << 4)) << 14) + o4;
    #pragma unroll
    for (int j = 0; j < 4; ++j) {
        const float4 v0 = f0[j], v1 = f1[j], v2 = f2[j], v3 = f3[j];
        of[(4 * j + 0) << 14] = make_float4(v0.x, v1.x, v2.x, v3.x);
        of[(4 * j + 1) << 14] = make_float4(v0.y, v1.y, v2.y, v3.y);
        of[(4 * j + 2) << 14] = make_float4(v0.z, v1.z, v2.z, v3.z);
        of[(4 * j + 3) << 14] = make_float4(v0.w, v1.w, v2.w, v3.w);
    }
}

extern "C" void kernel_launch(void* const* d_in, const int* in_sizes, int n_in,
                              void* d_out, int out_size) {
    const float* xyz  = (const float*)d_in[0];
    const float* feat = (const float*)d_in[1];
    float* out = (float*)d_out;

    build_kernel<<<NB, 1024>>>(xyz);
    query_kernel<<<(NB * NP) / QW, 32 * QW>>>(xyz);
    gather_xyz_kernel<<<(NB * NP * 4) / 256, 256>>>(xyz, out);
    gather_feat_kernel<<<(NB * NP * KOUT) / 256, 256>>>(feat, out);
}